// round 3
// baseline (speedup 1.0000x reference)
#include <cuda_runtime.h>
#include <cstdint>

#define Tn 168
#define Pn 16
#define Hn 24
#define Gn 96
#define Bn 8192
#define TPE 16                // threads per element-group (8 gate-owners x 2 k-halves)
#define GRP 14                // groups per CTA
#define En 2                  // elements per group-thread
#define EPC (GRP*En)          // 28 elements per CTA
#define NTHREADS (GRP*TPE)    // 224
#define XSTRIDE 20            // padded x row (floats)
#define HSTRIDE 28            // padded h row (floats)

// ---- packed f32x2 helpers ----
__device__ __forceinline__ unsigned long long pk2(float lo, float hi) {
    unsigned long long r;
    asm("mov.b64 %0, {%1, %2};" : "=l"(r) : "f"(lo), "f"(hi));
    return r;
}
__device__ __forceinline__ void fma2(unsigned long long& d, unsigned long long a, unsigned long long b) {
    asm("fma.rn.f32x2 %0, %1, %2, %0;" : "+l"(d) : "l"(a), "l"(b));
}
__device__ __forceinline__ void unpk2(unsigned long long v, float& lo, float& hi) {
    asm("mov.b64 {%0, %1}, %2;" : "=f"(lo), "=f"(hi) : "l"(v));
}

__device__ __forceinline__ float sigf(float x) {
    return __fdividef(1.0f, 1.0f + __expf(-x));
}
__device__ __forceinline__ float tanhfast(float x) {
    return 1.0f - __fdividef(2.0f, 1.0f + __expf(2.0f * x));
}

__global__ __launch_bounds__(NTHREADS, 2)
void lstm_fused_kernel(const float* __restrict__ x,
                       const float* __restrict__ Wih,   // [96,16]
                       const float* __restrict__ Whh,   // [96,24]
                       const float* __restrict__ bih,   // [96]
                       const float* __restrict__ bhh,   // [96]
                       const float* __restrict__ Wlin,  // [24,24]
                       const float* __restrict__ blin,  // [24]
                       float* __restrict__ out)         // [8192,24]
{
    // Weight layout: owner-major columns. Gate (type tt, unit j) lives at
    // column own = (j/3)*12 + tt*3 + (j%3); thread l8 owns columns [l8*12, l8*12+12).
    __shared__ float sWih[Pn * Gn];     // [p][own]
    __shared__ float sWhh[Hn * Gn];     // [k][own]
    __shared__ float sWlin[Hn * Hn];    // [j][m]
    __shared__ float sBlin[Hn];
    __shared__ float sX[2][EPC * XSTRIDE];
    __shared__ float sH[2][EPC * HSTRIDE];

    const int tid    = threadIdx.x;
    const int g16    = tid / TPE;        // 0..13 element group
    const int lane16 = tid % TPE;        // 0..15
    const int kh     = lane16 >> 3;      // 0/1: reduction half
    const int l8     = lane16 & 7;       // gate owner
    const int el0    = g16 * En;
    const int eg0    = blockIdx.x * EPC + el0;
    const int j0     = l8 * 3;

    // ---- prologue: stage + reorder weights ----
    for (int i = tid; i < Pn * Gn; i += NTHREADS) {
        int g = i >> 4, p = i & 15;
        int tt = g / Hn, j = g - tt * Hn;
        int own = (j / 3) * 12 + tt * 3 + (j % 3);
        sWih[p * Gn + own] = Wih[i];
    }
    for (int i = tid; i < Hn * Gn; i += NTHREADS) {
        int g = i / Hn, k = i - g * Hn;
        int tt = g / Hn, j = g - tt * Hn;
        int own = (j / 3) * 12 + tt * 3 + (j % 3);
        sWhh[k * Gn + own] = Whh[i];
    }
    for (int i = tid; i < Hn * Hn; i += NTHREADS) {
        int m = i / Hn, j = i - m * Hn;
        sWlin[j * Hn + m] = Wlin[i];
    }
    for (int i = tid; i < Hn; i += NTHREADS) sBlin[i] = blin[i];
    for (int i = tid; i < EPC * HSTRIDE; i += NTHREADS) { sH[0][i] = 0.0f; sH[1][i] = 0.0f; }

    // per-thread packed bias (only kh==0 carries it; kh==1 contributes zero)
    unsigned long long bias[6];
    {
        float bv[12];
#pragma unroll
        for (int q = 0; q < 12; q++) {
            int tt = q / 3;
            int g = tt * Hn + j0 + (q - tt * 3);
            bv[q] = (kh == 0) ? (bih[g] + bhh[g]) : 0.0f;
        }
#pragma unroll
        for (int s = 0; s < 6; s++) bias[s] = pk2(bv[2 * s], bv[2 * s + 1]);
    }

    // x(t=0): group of 16 threads stages 2 elements x 8 float2; e = kh here
    {
        float2 v = make_float2(0.0f, 0.0f);
        int eg = eg0 + kh;
        if (eg < Bn) v = *reinterpret_cast<const float2*>(&x[(size_t)eg * (Tn * Pn) + l8 * 2]);
        sX[0][(el0 + kh) * XSTRIDE + l8 * 2]     = v.x;
        sX[0][(el0 + kh) * XSTRIDE + l8 * 2 + 1] = v.y;
    }
    __syncthreads();

    // per-thread weight views: rows split by kh, cols by l8 (16B aligned)
    const ulonglong2* wih2 = reinterpret_cast<const ulonglong2*>(&sWih[l8 * 12]) + kh * 8 * 24;
    const ulonglong2* whh2 = reinterpret_cast<const ulonglong2*>(&sWhh[l8 * 12]) + kh * 12 * 24;

    float c[En][3];
    float hown[En][3];
#pragma unroll
    for (int e = 0; e < En; e++)
#pragma unroll
        for (int q = 0; q < 3; q++) { c[e][q] = 0.0f; hown[e][q] = 0.0f; }

    for (int t = 0; t < Tn; t++) {
        const int buf = t & 1;
        const int nbuf = buf ^ 1;

        // prefetch x(t+1)
        float2 xpf = make_float2(0.0f, 0.0f);
        {
            int eg = eg0 + kh;
            if (t + 1 < Tn && eg < Bn)
                xpf = *reinterpret_cast<const float2*>(
                    &x[(size_t)eg * (Tn * Pn) + (t + 1) * Pn + l8 * 2]);
        }

        // h(t-1): only this thread's 12 k's (3x LDS.128 per element)
        float hr[En][12];
#pragma unroll
        for (int e = 0; e < En; e++) {
            const float4* hv = reinterpret_cast<const float4*>(
                &sH[buf][(el0 + e) * HSTRIDE + kh * 12]);
#pragma unroll
            for (int s = 0; s < 3; s++) {
                float4 v = hv[s];
                hr[e][4 * s] = v.x; hr[e][4 * s + 1] = v.y;
                hr[e][4 * s + 2] = v.z; hr[e][4 * s + 3] = v.w;
            }
        }

        // partial gate pre-activations over this thread's row-half
        unsigned long long acc[En][6];
#pragma unroll
        for (int e = 0; e < En; e++)
#pragma unroll
            for (int s = 0; s < 6; s++) acc[e][s] = bias[s];

#pragma unroll
        for (int pp = 0; pp < 8; pp++) {
            ulonglong2 w0 = wih2[pp * 24];
            ulonglong2 w1 = wih2[pp * 24 + 1];
            ulonglong2 w2 = wih2[pp * 24 + 2];
            const int p = kh * 8 + pp;
#pragma unroll
            for (int e = 0; e < En; e++) {
                float xv = sX[buf][(el0 + e) * XSTRIDE + p];
                unsigned long long xs = pk2(xv, xv);
                fma2(acc[e][0], xs, w0.x);
                fma2(acc[e][1], xs, w0.y);
                fma2(acc[e][2], xs, w1.x);
                fma2(acc[e][3], xs, w1.y);
                fma2(acc[e][4], xs, w2.x);
                fma2(acc[e][5], xs, w2.y);
            }
        }
#pragma unroll
        for (int kk = 0; kk < 12; kk++) {
            ulonglong2 w0 = whh2[kk * 24];
            ulonglong2 w1 = whh2[kk * 24 + 1];
            ulonglong2 w2 = whh2[kk * 24 + 2];
#pragma unroll
            for (int e = 0; e < En; e++) {
                unsigned long long hs = pk2(hr[e][kk], hr[e][kk]);
                fma2(acc[e][0], hs, w0.x);
                fma2(acc[e][1], hs, w0.y);
                fma2(acc[e][2], hs, w1.x);
                fma2(acc[e][3], hs, w1.y);
                fma2(acc[e][4], hs, w2.x);
                fma2(acc[e][5], hs, w2.y);
            }
        }

        // cross-half reduction: butterfly over lane bit 3 (kh partner)
        float v[En][12];
#pragma unroll
        for (int e = 0; e < En; e++) {
#pragma unroll
            for (int s = 0; s < 6; s++) unpk2(acc[e][s], v[e][2 * s], v[e][2 * s + 1]);
#pragma unroll
            for (int q = 0; q < 12; q++)
                v[e][q] += __shfl_xor_sync(0xffffffffu, v[e][q], 8);
        }

        // elementwise on kh==0 lanes only (c-state lives there)
        if (kh == 0) {
#pragma unroll
            for (int e = 0; e < En; e++) {
#pragma unroll
                for (int q = 0; q < 3; q++) {
                    float iv = sigf(v[e][q]);
                    float fv = sigf(v[e][3 + q]);
                    float gv = tanhfast(v[e][6 + q]);
                    float ov = sigf(v[e][9 + q]);
                    c[e][q] = fv * c[e][q] + iv * gv;
                    float hval = ov * tanhfast(c[e][q]);
                    hown[e][q] = hval;
                    sH[nbuf][(el0 + e) * HSTRIDE + j0 + q] = hval;
                }
            }
        }

        // stage prefetched x
        if (t + 1 < Tn) {
            sX[nbuf][(el0 + kh) * XSTRIDE + l8 * 2]     = xpf.x;
            sX[nbuf][(el0 + kh) * XSTRIDE + l8 * 2 + 1] = xpf.y;
        }
        __syncthreads();   // h(t), x(t+1) visible
    }

    // ---- epilogue: out = tanh(h_last) @ Wlin^T + blin ----
    if (kh == 0) {
#pragma unroll
        for (int e = 0; e < En; e++)
#pragma unroll
            for (int q = 0; q < 3; q++)
                sH[0][(el0 + e) * HSTRIDE + j0 + q] = tanhfast(hown[e][q]);
    }
    __syncthreads();

    {
        // 48 outputs per group (2 elems x 24) over 16 threads -> 3 each
#pragma unroll
        for (int q = 0; q < 3; q++) {
            int idx = lane16 * 3 + q;      // 0..47
            int e   = idx / Hn;
            int m   = idx - e * Hn;
            int eg  = eg0 + e;
            float a = sBlin[m];
            const float* th = &sH[0][(el0 + e) * HSTRIDE];
#pragma unroll
            for (int j = 0; j < Hn; j++)
                a += th[j] * sWlin[j * Hn + m];
            if (eg < Bn) out[(size_t)eg * Hn + m] = a;
        }
    }
}

extern "C" void kernel_launch(void* const* d_in, const int* in_sizes, int n_in,
                              void* d_out, int out_size) {
    const float* x    = (const float*)d_in[0];
    const float* Wih  = (const float*)d_in[1];
    const float* Whh  = (const float*)d_in[2];
    const float* bih  = (const float*)d_in[3];
    const float* bhh  = (const float*)d_in[4];
    const float* Wlin = (const float*)d_in[5];
    const float* blin = (const float*)d_in[6];
    float* out = (float*)d_out;

    const int grid = (Bn + EPC - 1) / EPC;  // 293 -> ~2 CTAs per SM
    lstm_fused_kernel<<<grid, NTHREADS>>>(x, Wih, Whh, bih, bhh, Wlin, blin, out);
}

// round 4
// speedup vs baseline: 1.3719x; 1.3719x over previous
#include <cuda_runtime.h>
#include <cstdint>

#define Tn 168
#define Pn 16
#define Hn 24
#define Gn 96
#define Bn 8192
#define TPE 8                 // threads per element-group (one group = 8 lanes, intra-warp)
#define GRP 28                // groups per CTA
#define En 2                  // elements per thread
#define EPC (GRP*En)          // 56 elements per CTA
#define NTHREADS (GRP*TPE)    // 224
#define XSTRIDE 20            // padded x row (floats)
#define HSTRIDE 28            // padded h row (floats)

// ---- packed f32x2 helpers ----
__device__ __forceinline__ unsigned long long pk2(float lo, float hi) {
    unsigned long long r;
    asm("mov.b64 %0, {%1, %2};" : "=l"(r) : "f"(lo), "f"(hi));
    return r;
}
__device__ __forceinline__ void fma2(unsigned long long& d, unsigned long long a, unsigned long long b) {
    asm("fma.rn.f32x2 %0, %1, %2, %0;" : "+l"(d) : "l"(a), "l"(b));
}
__device__ __forceinline__ void unpk2(unsigned long long v, float& lo, float& hi) {
    asm("mov.b64 {%0, %1}, %2;" : "=f"(lo), "=f"(hi) : "l"(v));
}

// single-instruction MUFU.TANH
__device__ __forceinline__ float tanhapx(float x) {
    float y;
    asm("tanh.approx.f32 %0, %1;" : "=f"(y) : "f"(x));
    return y;
}

__global__ __launch_bounds__(NTHREADS, 1)
void lstm_fused_kernel(const float* __restrict__ x,
                       const float* __restrict__ Wih,   // [96,16]
                       const float* __restrict__ Whh,   // [96,24]
                       const float* __restrict__ bih,   // [96]
                       const float* __restrict__ bhh,   // [96]
                       const float* __restrict__ Wlin,  // [24,24]
                       const float* __restrict__ blin,  // [24]
                       float* __restrict__ out)         // [8192,24]
{
    // Owner-major weight columns: gate (type tt, unit j) -> col (j/3)*12 + tt*3 + j%3.
    // i/f/o rows (tt != 2) pre-scaled by 0.5 so sigmoid(x) = 0.5*tanh(g') + 0.5
    // with g' = 0.5*(pre-activation) computed for free inside the dot product.
    __shared__ float sWih[Pn * Gn];     // [p][own]
    __shared__ float sWhh[Hn * Gn];     // [k][own]
    __shared__ float sWlin[Hn * Hn];    // [j][m]
    __shared__ float sBlin[Hn];
    __shared__ float sX[2][EPC * XSTRIDE];
    __shared__ float sH[2][EPC * HSTRIDE];

    const int tid = threadIdx.x;
    const int grp = tid / TPE;          // 0..27 (4 groups per warp)
    const int l8  = tid % TPE;          // 0..7 gate owner
    const int el0 = grp * En;
    const int eg0 = blockIdx.x * EPC + el0;
    const int j0  = l8 * 3;

    // ---- prologue: stage + reorder + pre-scale weights ----
    for (int i = tid; i < Pn * Gn; i += NTHREADS) {
        int g = i >> 4, p = i & 15;
        int tt = g / Hn, j = g - tt * Hn;
        int own = (j / 3) * 12 + tt * 3 + (j % 3);
        float scale = (tt == 2) ? 1.0f : 0.5f;
        sWih[p * Gn + own] = Wih[i] * scale;
    }
    for (int i = tid; i < Hn * Gn; i += NTHREADS) {
        int g = i / Hn, k = i - g * Hn;
        int tt = g / Hn, j = g - tt * Hn;
        int own = (j / 3) * 12 + tt * 3 + (j % 3);
        float scale = (tt == 2) ? 1.0f : 0.5f;
        sWhh[k * Gn + own] = Whh[i] * scale;
    }
    for (int i = tid; i < Hn * Hn; i += NTHREADS) {
        int m = i / Hn, j = i - m * Hn;
        sWlin[j * Hn + m] = Wlin[i];
    }
    for (int i = tid; i < Hn; i += NTHREADS) sBlin[i] = blin[i];
    for (int i = tid; i < EPC * HSTRIDE; i += NTHREADS) { sH[0][i] = 0.0f; sH[1][i] = 0.0f; }

    // per-thread packed bias (same 0.5 pre-scale for i/f/o)
    unsigned long long bias[6];
    {
        float bv[12];
#pragma unroll
        for (int q = 0; q < 12; q++) {
            int tt = q / 3;
            int g = tt * Hn + j0 + (q - tt * 3);
            float scale = (tt == 2) ? 1.0f : 0.5f;
            bv[q] = (bih[g] + bhh[g]) * scale;
        }
#pragma unroll
        for (int s = 0; s < 6; s++) bias[s] = pk2(bv[2 * s], bv[2 * s + 1]);
    }

    // x(t=0)
#pragma unroll
    for (int e = 0; e < En; e++) {
        float2 v = make_float2(0.0f, 0.0f);
        int eg = eg0 + e;
        if (eg < Bn) v = *reinterpret_cast<const float2*>(&x[(size_t)eg * (Tn * Pn) + l8 * 2]);
        sX[0][(el0 + e) * XSTRIDE + l8 * 2]     = v.x;
        sX[0][(el0 + e) * XSTRIDE + l8 * 2 + 1] = v.y;
    }
    __syncthreads();   // weights staged (only CTA-wide barrier)

    const ulonglong2* wih2 = reinterpret_cast<const ulonglong2*>(&sWih[l8 * 12]); // + p*24
    const ulonglong2* whh2 = reinterpret_cast<const ulonglong2*>(&sWhh[l8 * 12]); // + k*24

    float c[En][3];
    float hown[En][3];
#pragma unroll
    for (int e = 0; e < En; e++)
#pragma unroll
        for (int q = 0; q < 3; q++) { c[e][q] = 0.0f; hown[e][q] = 0.0f; }

    for (int t = 0; t < Tn; t++) {
        const int buf = t & 1;
        const int nbuf = buf ^ 1;

        // prefetch x(t+1)
        float2 xpf[En];
#pragma unroll
        for (int e = 0; e < En; e++) {
            xpf[e] = make_float2(0.0f, 0.0f);
            int eg = eg0 + e;
            if (t + 1 < Tn && eg < Bn)
                xpf[e] = *reinterpret_cast<const float2*>(
                    &x[(size_t)eg * (Tn * Pn) + (t + 1) * Pn + l8 * 2]);
        }

        // h(t-1) -> regs (broadcast float4 LDS)
        float hr[En][Hn];
#pragma unroll
        for (int e = 0; e < En; e++) {
            const float4* hv = reinterpret_cast<const float4*>(&sH[buf][(el0 + e) * HSTRIDE]);
#pragma unroll
            for (int s = 0; s < 6; s++) {
                float4 v = hv[s];
                hr[e][4 * s] = v.x; hr[e][4 * s + 1] = v.y;
                hr[e][4 * s + 2] = v.z; hr[e][4 * s + 3] = v.w;
            }
        }

        // gate pre-activations (weights loaded once, used for En elements)
        unsigned long long acc[En][6];
#pragma unroll
        for (int e = 0; e < En; e++)
#pragma unroll
            for (int s = 0; s < 6; s++) acc[e][s] = bias[s];

#pragma unroll
        for (int p = 0; p < Pn; p++) {
            ulonglong2 w0 = wih2[p * 24];
            ulonglong2 w1 = wih2[p * 24 + 1];
            ulonglong2 w2 = wih2[p * 24 + 2];
#pragma unroll
            for (int e = 0; e < En; e++) {
                float xv = sX[buf][(el0 + e) * XSTRIDE + p];
                unsigned long long xs = pk2(xv, xv);
                fma2(acc[e][0], xs, w0.x);
                fma2(acc[e][1], xs, w0.y);
                fma2(acc[e][2], xs, w1.x);
                fma2(acc[e][3], xs, w1.y);
                fma2(acc[e][4], xs, w2.x);
                fma2(acc[e][5], xs, w2.y);
            }
        }
#pragma unroll
        for (int k = 0; k < Hn; k++) {
            ulonglong2 w0 = whh2[k * 24];
            ulonglong2 w1 = whh2[k * 24 + 1];
            ulonglong2 w2 = whh2[k * 24 + 2];
#pragma unroll
            for (int e = 0; e < En; e++) {
                unsigned long long hs = pk2(hr[e][k], hr[e][k]);
                fma2(acc[e][0], hs, w0.x);
                fma2(acc[e][1], hs, w0.y);
                fma2(acc[e][2], hs, w1.x);
                fma2(acc[e][3], hs, w1.y);
                fma2(acc[e][4], hs, w2.x);
                fma2(acc[e][5], hs, w2.y);
            }
        }

        // thread-local elementwise: 1 MUFU.TANH per activation
#pragma unroll
        for (int e = 0; e < En; e++) {
            float v[12];
#pragma unroll
            for (int s = 0; s < 6; s++) unpk2(acc[e][s], v[2 * s], v[2 * s + 1]);
#pragma unroll
            for (int q = 0; q < 3; q++) {
                float iv = fmaf(tanhapx(v[q]),     0.5f, 0.5f);
                float fv = fmaf(tanhapx(v[3 + q]), 0.5f, 0.5f);
                float gv = tanhapx(v[6 + q]);
                float ov = fmaf(tanhapx(v[9 + q]), 0.5f, 0.5f);
                c[e][q] = fv * c[e][q] + iv * gv;
                float hval = ov * tanhapx(c[e][q]);
                hown[e][q] = hval;
                sH[nbuf][(el0 + e) * HSTRIDE + j0 + q] = hval;
            }
        }

        // stage prefetched x
        if (t + 1 < Tn) {
#pragma unroll
            for (int e = 0; e < En; e++) {
                sX[nbuf][(el0 + e) * XSTRIDE + l8 * 2]     = xpf[e].x;
                sX[nbuf][(el0 + e) * XSTRIDE + l8 * 2 + 1] = xpf[e].y;
            }
        }
        // h/x exchange is entirely intra-warp (group = 8 lanes, 4 groups/warp):
        // warp-level sync only -> warps free-run and overlap phases across the SM.
        __syncwarp();
    }

    // ---- epilogue: out = tanh(h_last) @ Wlin^T + blin (intra-warp exchange) ----
#pragma unroll
    for (int e = 0; e < En; e++)
#pragma unroll
        for (int q = 0; q < 3; q++)
            sH[1][(el0 + e) * HSTRIDE + j0 + q] = tanhapx(hown[e][q]);
    __syncwarp();

    {
        const int m0 = l8 * 3;
#pragma unroll
        for (int e = 0; e < En; e++) {
            int eg = eg0 + e;
            float a0 = sBlin[m0], a1 = sBlin[m0 + 1], a2 = sBlin[m0 + 2];
            const float* th = &sH[1][(el0 + e) * HSTRIDE];
#pragma unroll
            for (int j = 0; j < Hn; j++) {
                float tv = th[j];
                a0 += tv * sWlin[j * Hn + m0];
                a1 += tv * sWlin[j * Hn + m0 + 1];
                a2 += tv * sWlin[j * Hn + m0 + 2];
            }
            if (eg < Bn) {
                out[(size_t)eg * Hn + m0]     = a0;
                out[(size_t)eg * Hn + m0 + 1] = a1;
                out[(size_t)eg * Hn + m0 + 2] = a2;
            }
        }
    }
}

extern "C" void kernel_launch(void* const* d_in, const int* in_sizes, int n_in,
                              void* d_out, int out_size) {
    const float* x    = (const float*)d_in[0];
    const float* Wih  = (const float*)d_in[1];
    const float* Whh  = (const float*)d_in[2];
    const float* bih  = (const float*)d_in[3];
    const float* bhh  = (const float*)d_in[4];
    const float* Wlin = (const float*)d_in[5];
    const float* blin = (const float*)d_in[6];
    float* out = (float*)d_out;

    const int grid = (Bn + EPC - 1) / EPC;  // 147 -> 1 CTA per SM
    lstm_fused_kernel<<<grid, NTHREADS>>>(x, Wih, Whh, bih, bhh, Wlin, blin, out);
}